// round 6
// baseline (speedup 1.0000x reference)
#include <cuda_runtime.h>
#include <cuda_bf16.h>
#include <cstdint>
#include <cstddef>

// Problem constants
#define N_SRC0   286000
#define N_DST0   11000
#define N_E0     275000
#define N_DST1   1000
#define N_E1     10000
#define F_IN     602
#define HID      256
#define NCLS     41
#define KPAD     640          // 20 chunks of 32
#define F2       (F_IN / 2)   // 301
#define P2       (KPAD / 2)   // 320

// ---------------- scratch (device globals; no runtime allocation) ----------
__device__ int g_cnt0[N_DST0];
__device__ int g_cur0[N_DST0];
__device__ int g_off0[N_DST0 + 1];
__device__ int g_src0[N_E0];
__device__ int g_cnt1[N_DST1];
__device__ int g_cur1[N_DST1];
__device__ int g_off1[N_DST1 + 1];
__device__ int g_src1[N_E1];

__device__ __align__(16) __nv_bfloat16 g_xhi[(size_t)N_DST0 * KPAD];
__device__ __align__(16) __nv_bfloat16 g_xlo[(size_t)N_DST0 * KPAD];
__device__ __align__(16) __nv_bfloat16 g_ahi[(size_t)N_DST0 * KPAD];
__device__ __align__(16) __nv_bfloat16 g_alo[(size_t)N_DST0 * KPAD];
__device__ __align__(16) __nv_bfloat16 g_wshi[256 * KPAD];   // [n][k]  (W^T)
__device__ __align__(16) __nv_bfloat16 g_wslo[256 * KPAD];
__device__ __align__(16) __nv_bfloat16 g_wnhi[256 * KPAD];
__device__ __align__(16) __nv_bfloat16 g_wnlo[256 * KPAD];

__device__ float g_h    [(size_t)N_DST0 * HID];
__device__ float g_hagg1[(size_t)N_DST1 * HID];

__device__ __forceinline__ void split_bf16(float v, __nv_bfloat16& h, __nv_bfloat16& l) {
    h = __float2bfloat16(v);
    l = __float2bfloat16(v - __bfloat162float(h));
}

// ---------------- CSR build --------------------------------------------------
__global__ void k_zero() {
    int i = blockIdx.x * blockDim.x + threadIdx.x;
    if (i < N_DST0) { g_cnt0[i] = 0; g_cur0[i] = 0; }
    if (i < N_DST1) { g_cnt1[i] = 0; g_cur1[i] = 0; }
}

// fused: edge counting + weight hi/lo prep (independent work, one launch)
#define CNT_BLKS  ((N_E0 + 255) / 256)           // 1075
#define PW_BLKS   ((2 * 256 * KPAD + 255) / 256) // 1280
__global__ void k_count_prepw(const int* __restrict__ e0_dst, const int* __restrict__ e1_dst,
                              const float* __restrict__ Ws, const float* __restrict__ Wn) {
    int bx = blockIdx.x;
    if (bx < CNT_BLKS) {
        int i = bx * 256 + threadIdx.x;
        if (i < N_E0) atomicAdd(&g_cnt0[e0_dst[i]], 1);
        if (i < N_E1) atomicAdd(&g_cnt1[e1_dst[i]], 1);
    } else {
        int idx = (bx - CNT_BLKS) * 256 + threadIdx.x;
        if (idx >= 2 * 256 * KPAD) return;
        int m = idx / (256 * KPAD);
        int r = idx % (256 * KPAD);
        int n = r / KPAD;
        int k = r % KPAD;
        const float* W = m ? Wn : Ws;
        float v = (k < F_IN) ? W[(size_t)k * HID + n] : 0.0f;
        __nv_bfloat16 h, l; split_bf16(v, h, l);
        if (m) { g_wnhi[n * KPAD + k] = h; g_wnlo[n * KPAD + k] = l; }
        else   { g_wshi[n * KPAD + k] = h; g_wslo[n * KPAD + k] = l; }
    }
}

__device__ void scan_excl(const int* cnt, int* off, int n) {
    __shared__ int wsum[32];
    __shared__ int carry;
    const int t = threadIdx.x, lane = t & 31, w = t >> 5;
    if (t == 0) carry = 0;
    __syncthreads();
    for (int base = 0; base < n; base += 1024) {
        int i = base + t;
        int v = (i < n) ? cnt[i] : 0;
        int s = v;
        #pragma unroll
        for (int d = 1; d < 32; d <<= 1) { int u = __shfl_up_sync(~0u, s, d); if (lane >= d) s += u; }
        if (lane == 31) wsum[w] = s;
        __syncthreads();
        if (w == 0) {
            int ws = wsum[lane];
            #pragma unroll
            for (int d = 1; d < 32; d <<= 1) { int u = __shfl_up_sync(~0u, ws, d); if (lane >= d) ws += u; }
            wsum[lane] = ws;
        }
        __syncthreads();
        int woff = (w > 0) ? wsum[w - 1] : 0;
        if (i < n) off[i] = carry + woff + s - v;
        __syncthreads();
        if (t == 0) carry += wsum[31];
        __syncthreads();
    }
    if (threadIdx.x == 0) off[n] = carry;
}

__global__ void k_scan() {
    if (blockIdx.x == 0) scan_excl(g_cnt0, g_off0, N_DST0);
    else                 scan_excl(g_cnt1, g_off1, N_DST1);
}

// fused: edge scatter + x hi/lo prep
#define PX_BLKS ((N_DST0 * P2 + 255) / 256)   // 13750
__global__ void k_scatter_prepx(const int* __restrict__ e0_src, const int* __restrict__ e0_dst,
                                const int* __restrict__ e1_src, const int* __restrict__ e1_dst,
                                const float* __restrict__ x) {
    int bx = blockIdx.x;
    if (bx < CNT_BLKS) {
        int i = bx * 256 + threadIdx.x;
        if (i < N_E0) {
            int d = e0_dst[i];
            int p = atomicAdd(&g_cur0[d], 1);
            g_src0[g_off0[d] + p] = e0_src[i];
        }
        if (i < N_E1) {
            int d = e1_dst[i];
            int p = atomicAdd(&g_cur1[d], 1);
            g_src1[g_off1[d] + p] = e1_src[i];
        }
    } else {
        int idx = (bx - CNT_BLKS) * 256 + threadIdx.x;
        if (idx >= N_DST0 * P2) return;
        int row = idx / P2;
        int p   = idx % P2;
        float2 v = make_float2(0.f, 0.f);
        if (p < F2) v = reinterpret_cast<const float2*>(x)[(size_t)row * F2 + p];
        __nv_bfloat16 hx, lx, hy, ly;
        split_bf16(v.x, hx, lx);
        split_bf16(v.y, hy, ly);
        __nv_bfloat162 hp; hp.x = hx; hp.y = hy;
        __nv_bfloat162 lp; lp.x = lx; lp.y = ly;
        reinterpret_cast<__nv_bfloat162*>(g_xhi)[(size_t)row * P2 + p] = hp;
        reinterpret_cast<__nv_bfloat162*>(g_xlo)[(size_t)row * P2 + p] = lp;
    }
}

// ---------------- GEMM building blocks (mma.sync HMMA) ----------------------
#define BK        32
#define ROWP      40                       // padded row length (bf16)
#define A_TERM    (128 * ROWP * 2)         // 10240 B
#define B_TERM    (64 * ROWP * 2)          // 5120 B
#define BUF_SZ    (2 * A_TERM + 2 * B_TERM)  // 30720 B
#define GEMM_SMEM (2 * BUF_SZ)             // 61440 B
#define NCH       20                       // K chunks per phase
#define MBLK      ((N_DST0 + 127) / 128)   // 86
#define GEMM_BLKS (MBLK * 4)               // 344

#define CP16(dst, src, pred) \
    asm volatile("cp.async.cg.shared.global [%0], [%1], 16, %2;" \
                 :: "r"(dst), "l"(src), "r"(pred))
#define CP_COMMIT() asm volatile("cp.async.commit_group;" ::: "memory")
#define CP_WAIT(n)  asm volatile("cp.async.wait_group %0;" :: "n"(n) : "memory")

__device__ __forceinline__ uint32_t smem_u32(const void* p) {
    uint32_t a;
    asm("{ .reg .u64 t; cvta.to.shared.u64 t, %1; cvt.u32.u64 %0, t; }" : "=r"(a) : "l"(p));
    return a;
}

__device__ __forceinline__ void mma_bf16(float* d,
                                         const uint32_t* a, const uint32_t* b) {
    asm volatile(
        "mma.sync.aligned.m16n8k16.row.col.f32.bf16.bf16.f32 "
        "{%0,%1,%2,%3}, {%4,%5,%6,%7}, {%8,%9}, {%0,%1,%2,%3};"
        : "+f"(d[0]), "+f"(d[1]), "+f"(d[2]), "+f"(d[3])
        : "r"(a[0]), "r"(a[1]), "r"(a[2]), "r"(a[3]), "r"(b[0]), "r"(b[1]));
}

__device__ __forceinline__ void gemm_block(
    char* smem, int rowBase, int colBase,
    const __nv_bfloat16* __restrict__ Ah, const __nv_bfloat16* __restrict__ Al,
    const __nv_bfloat16* __restrict__ Bh, const __nv_bfloat16* __restrict__ Bl,
    const float* __restrict__ bias, int fuse)
{
    const uint32_t sb = smem_u32(smem);
    const int tid  = threadIdx.x;
    const int lane = tid & 31;
    const int wid  = tid >> 5;
    const int warpM = wid & 3;            // 0..3
    const int warpN = wid >> 2;           // 0..1
    const int g  = lane >> 2;             // 0..7
    const int tg = lane & 3;              // 0..3

    auto issue = [&](int c) {
        const int kb = c * BK;
        const uint32_t bufb = sb + (uint32_t)(c & 1) * BUF_SZ;
        #pragma unroll
        for (int u = 0; u < 2; ++u) {
            int idx = tid + u * 256;          // 0..511
            int row = idx >> 2, v = idx & 3;
            int grow = rowBase + row;
            int pr = (grow < N_DST0) ? 16 : 0;
            size_t gb = ((size_t)grow * KPAD + kb + v * 8) * 2;
            if (grow >= N_DST0) gb = 0;
            uint32_t so = bufb + (uint32_t)(row * (ROWP * 2) + v * 16);
            CP16(so,          (const char*)Ah + gb, pr);
            CP16(so + A_TERM, (const char*)Al + gb, pr);
        }
        {
            int row = tid >> 2, v = tid & 3;
            size_t gb = ((size_t)(colBase + row) * KPAD + kb + v * 8) * 2;
            uint32_t so = bufb + (uint32_t)(2 * A_TERM + row * (ROWP * 2) + v * 16);
            CP16(so,          (const char*)Bh + gb, 16);
            CP16(so + B_TERM, (const char*)Bl + gb, 16);
        }
    };

    float acc[2][4][4] = {};   // [mtile][ntile][reg]

    issue(0);
    CP_COMMIT();

    for (int c = 0; c < NCH; ++c) {
        if (c + 1 < NCH) { issue(c + 1); CP_COMMIT(); CP_WAIT(1); }
        else             { CP_WAIT(0); }
        __syncthreads();

        const char* buf = smem + (c & 1) * BUF_SZ;
        const char* Ahs = buf;
        const char* Als = buf + A_TERM;
        const char* Bhs = buf + 2 * A_TERM;
        const char* Bls = buf + 2 * A_TERM + B_TERM;

        #pragma unroll
        for (int kk = 0; kk < BK; kk += 16) {
            const int kbyte = kk * 2 + tg * 4;

            uint32_t aH[2][4];
            #pragma unroll
            for (int mt = 0; mt < 2; ++mt) {
                int r0 = warpM * 32 + mt * 16 + g;
                aH[mt][0] = *(const uint32_t*)(Ahs + r0 * (ROWP * 2) + kbyte);
                aH[mt][1] = *(const uint32_t*)(Ahs + (r0 + 8) * (ROWP * 2) + kbyte);
                aH[mt][2] = *(const uint32_t*)(Ahs + r0 * (ROWP * 2) + kbyte + 16);
                aH[mt][3] = *(const uint32_t*)(Ahs + (r0 + 8) * (ROWP * 2) + kbyte + 16);
            }
            uint32_t bH[4][2];
            #pragma unroll
            for (int nt = 0; nt < 4; ++nt) {
                int r = warpN * 32 + nt * 8 + g;
                bH[nt][0] = *(const uint32_t*)(Bhs + r * (ROWP * 2) + kbyte);
                bH[nt][1] = *(const uint32_t*)(Bhs + r * (ROWP * 2) + kbyte + 16);
            }
            #pragma unroll
            for (int mt = 0; mt < 2; ++mt)
                #pragma unroll
                for (int nt = 0; nt < 4; ++nt)
                    mma_bf16(acc[mt][nt], aH[mt], bH[nt]);

            uint32_t bL[4][2];
            #pragma unroll
            for (int nt = 0; nt < 4; ++nt) {
                int r = warpN * 32 + nt * 8 + g;
                bL[nt][0] = *(const uint32_t*)(Bls + r * (ROWP * 2) + kbyte);
                bL[nt][1] = *(const uint32_t*)(Bls + r * (ROWP * 2) + kbyte + 16);
            }
            #pragma unroll
            for (int mt = 0; mt < 2; ++mt)
                #pragma unroll
                for (int nt = 0; nt < 4; ++nt)
                    mma_bf16(acc[mt][nt], aH[mt], bL[nt]);

            uint32_t aL[2][4];
            #pragma unroll
            for (int mt = 0; mt < 2; ++mt) {
                int r0 = warpM * 32 + mt * 16 + g;
                aL[mt][0] = *(const uint32_t*)(Als + r0 * (ROWP * 2) + kbyte);
                aL[mt][1] = *(const uint32_t*)(Als + (r0 + 8) * (ROWP * 2) + kbyte);
                aL[mt][2] = *(const uint32_t*)(Als + r0 * (ROWP * 2) + kbyte + 16);
                aL[mt][3] = *(const uint32_t*)(Als + (r0 + 8) * (ROWP * 2) + kbyte + 16);
            }
            #pragma unroll
            for (int mt = 0; mt < 2; ++mt)
                #pragma unroll
                for (int nt = 0; nt < 4; ++nt)
                    mma_bf16(acc[mt][nt], aL[mt], bH[nt]);
        }
        __syncthreads();
    }

    if (fuse) {
        float2 bv[4];
        #pragma unroll
        for (int nt = 0; nt < 4; ++nt) {
            int col = colBase + warpN * 32 + nt * 8 + tg * 2;
            bv[nt].x = __ldg(bias + col);
            bv[nt].y = __ldg(bias + col + 1);
        }
        #pragma unroll
        for (int mt = 0; mt < 2; ++mt) {
            #pragma unroll
            for (int half = 0; half < 2; ++half) {
                int row = rowBase + warpM * 32 + mt * 16 + g + half * 8;
                if (row >= N_DST0) continue;
                #pragma unroll
                for (int nt = 0; nt < 4; ++nt) {
                    int col = colBase + warpN * 32 + nt * 8 + tg * 2;
                    float* p = g_h + (size_t)row * HID + col;
                    float2 old = *(float2*)p;
                    float2 o;
                    o.x = fmaxf(acc[mt][nt][half * 2 + 0] + old.x + bv[nt].x, 0.f);
                    o.y = fmaxf(acc[mt][nt][half * 2 + 1] + old.y + bv[nt].y, 0.f);
                    *(float2*)p = o;
                }
            }
        }
    } else {
        #pragma unroll
        for (int mt = 0; mt < 2; ++mt) {
            #pragma unroll
            for (int half = 0; half < 2; ++half) {
                int row = rowBase + warpM * 32 + mt * 16 + g + half * 8;
                if (row >= N_DST0) continue;
                #pragma unroll
                for (int nt = 0; nt < 4; ++nt) {
                    int col = colBase + warpN * 32 + nt * 8 + tg * 2;
                    float2 o;
                    o.x = acc[mt][nt][half * 2 + 0];
                    o.y = acc[mt][nt][half * 2 + 1];
                    *(float2*)(g_h + (size_t)row * HID + col) = o;
                }
            }
        }
    }
}

// ---------------- layer-0 aggregation block (256 threads) --------------------
__device__ __forceinline__ void agg0_block(int dst, const float* __restrict__ x) {
    const int beg = g_off0[dst];
    const int end = g_off0[dst + 1];
    const int t   = threadIdx.x;          // 0..255; lane0=t, lane1=t+256

    float2 acc0 = make_float2(0.f, 0.f);
    float2 acc1 = make_float2(0.f, 0.f);
    const bool has1 = (t + 256) < F2;     // t < 45

    int e = beg;
    for (; e + 4 <= end; e += 4) {
        const float2* r0 = reinterpret_cast<const float2*>(x + (size_t)g_src0[e + 0] * F_IN);
        const float2* r1 = reinterpret_cast<const float2*>(x + (size_t)g_src0[e + 1] * F_IN);
        const float2* r2 = reinterpret_cast<const float2*>(x + (size_t)g_src0[e + 2] * F_IN);
        const float2* r3 = reinterpret_cast<const float2*>(x + (size_t)g_src0[e + 3] * F_IN);
        float2 a0 = __ldg(r0 + t), b0 = __ldg(r1 + t), c0 = __ldg(r2 + t), d0 = __ldg(r3 + t);
        acc0.x += a0.x + b0.x + c0.x + d0.x;
        acc0.y += a0.y + b0.y + c0.y + d0.y;
        if (has1) {
            float2 a1 = __ldg(r0 + t + 256), b1 = __ldg(r1 + t + 256);
            float2 c1 = __ldg(r2 + t + 256), d1 = __ldg(r3 + t + 256);
            acc1.x += a1.x + b1.x + c1.x + d1.x;
            acc1.y += a1.y + b1.y + c1.y + d1.y;
        }
    }
    for (; e < end; ++e) {
        const float2* row = reinterpret_cast<const float2*>(x + (size_t)g_src0[e] * F_IN);
        float2 v0 = __ldg(row + t);
        acc0.x += v0.x; acc0.y += v0.y;
        if (has1) {
            float2 v1 = __ldg(row + t + 256);
            acc1.x += v1.x; acc1.y += v1.y;
        }
    }

    const float inv = (end > beg) ? 1.0f / (float)(end - beg) : 0.0f;
    __nv_bfloat162* ohi = reinterpret_cast<__nv_bfloat162*>(g_ahi) + (size_t)dst * P2;
    __nv_bfloat162* olo = reinterpret_cast<__nv_bfloat162*>(g_alo) + (size_t)dst * P2;
    float2 accs[2] = {acc0, acc1};
    #pragma unroll
    for (int j = 0; j < 2; ++j) {
        int p = t + j * 256;
        if (p >= P2) break;
        float vx = (p < F2) ? accs[j].x * inv : 0.f;
        float vy = (p < F2) ? accs[j].y * inv : 0.f;
        __nv_bfloat16 hx, lx, hy, ly;
        split_bf16(vx, hx, lx);
        split_bf16(vy, hy, ly);
        __nv_bfloat162 hp; hp.x = hx; hp.y = hy;
        __nv_bfloat162 lp; lp.x = lx; lp.y = ly;
        ohi[p] = hp;
        olo[p] = lp;
    }
}

// ---------------- fused: x-phase GEMM (co-resident with) agg0 ----------------
__global__ __launch_bounds__(256, 3)
void k_fused_xgemm_agg0(const float* __restrict__ x, const float* __restrict__ bias) {
    extern __shared__ char smem[];
    int bx = blockIdx.x;
    if (bx < GEMM_BLKS) {
        // 4 consecutive blocks share a rowBase -> concurrent colBase, A hits L2
        int m = bx >> 2, n = bx & 3;
        gemm_block(smem, m * 128, n * 64, g_xhi, g_xlo, g_wshi, g_wslo, bias, 0);
    } else {
        agg0_block(bx - GEMM_BLKS, x);
    }
}

// standalone agg-phase GEMM (fused bias+relu epilogue)
__global__ __launch_bounds__(256, 3)
void k_gemm_agg(const float* __restrict__ bias) {
    extern __shared__ char smem[];
    int m = blockIdx.x >> 2, n = blockIdx.x & 3;
    gemm_block(smem, m * 128, n * 64, g_ahi, g_alo, g_wnhi, g_wnlo, bias, 1);
}

// ---------------- layer-1 mean aggregation -----------------------------------
__global__ void k_agg1() {
    const int dst = blockIdx.x;
    const int beg = g_off1[dst];
    const int end = g_off1[dst + 1];
    const int t   = threadIdx.x;

    float acc = 0.f;
    for (int e = beg; e < end; ++e)
        acc += g_h[(size_t)g_src1[e] * HID + t];

    const float inv = (end > beg) ? 1.0f / (float)(end - beg) : 0.0f;
    g_hagg1[(size_t)dst * HID + t] = acc * inv;
}

// ---------------- output layer -------------------------------------------------
__global__ void k_out(const float* __restrict__ Ws1,
                      const float* __restrict__ Wn1,
                      const float* __restrict__ b1,
                      float* __restrict__ out) {
    __shared__ float hd[HID];
    __shared__ float ha[HID];
    const int dst = blockIdx.x;
    for (int i = threadIdx.x; i < HID; i += blockDim.x) {
        hd[i] = g_h[(size_t)dst * HID + i];
        ha[i] = g_hagg1[(size_t)dst * HID + i];
    }
    __syncthreads();
    const int c = threadIdx.x;
    if (c < NCLS) {
        float s = b1[c];
        #pragma unroll 4
        for (int k = 0; k < HID; ++k)
            s += hd[k] * Ws1[k * NCLS + c] + ha[k] * Wn1[k * NCLS + c];
        out[dst * NCLS + c] = s;
    }
}

// ---------------- launch (single stream, graph-capture safe) -----------------
extern "C" void kernel_launch(void* const* d_in, const int* in_sizes, int n_in,
                              void* d_out, int out_size) {
    const float* x      = (const float*)d_in[0];
    const float* Wself0 = (const float*)d_in[1];
    const float* Wneigh0= (const float*)d_in[2];
    const float* b0     = (const float*)d_in[3];
    const float* Wself1 = (const float*)d_in[4];
    const float* Wneigh1= (const float*)d_in[5];
    const float* b1     = (const float*)d_in[6];
    const int*   e0_src = (const int*)d_in[7];
    const int*   e0_dst = (const int*)d_in[8];
    const int*   e1_src = (const int*)d_in[9];
    const int*   e1_dst = (const int*)d_in[10];
    float* out = (float*)d_out;

    static bool attr_set = false;
    if (!attr_set) {
        cudaFuncSetAttribute(k_fused_xgemm_agg0, cudaFuncAttributeMaxDynamicSharedMemorySize, GEMM_SMEM);
        cudaFuncSetAttribute(k_gemm_agg, cudaFuncAttributeMaxDynamicSharedMemorySize, GEMM_SMEM);
        attr_set = true;
    }

    k_zero            <<<(N_DST0 + 255) / 256, 256>>>();
    k_count_prepw     <<<CNT_BLKS + PW_BLKS, 256>>>(e0_dst, e1_dst, Wself0, Wneigh0);
    k_scan            <<<2, 1024>>>();
    k_scatter_prepx   <<<CNT_BLKS + PX_BLKS, 256>>>(e0_src, e0_dst, e1_src, e1_dst, x);
    k_fused_xgemm_agg0<<<GEMM_BLKS + N_DST0, 256, GEMM_SMEM>>>(x, b0);
    k_gemm_agg        <<<GEMM_BLKS, 256, GEMM_SMEM>>>(b0);
    k_agg1            <<<N_DST1, 256>>>();
    k_out             <<<N_DST1, 64>>>(Wself1, Wneigh1, b1, out);
}

// round 7
// speedup vs baseline: 1.1279x; 1.1279x over previous
#include <cuda_runtime.h>
#include <cuda_bf16.h>
#include <cstdint>
#include <cstddef>

// Problem constants
#define N_SRC0   286000
#define N_DST0   11000
#define N_E0     275000
#define N_DST1   1000
#define N_E1     10000
#define F_IN     602
#define HID      256
#define NCLS     41
#define KPAD     640          // 20 chunks of 32
#define F2       (F_IN / 2)   // 301
#define P2       (KPAD / 2)   // 320

// ---------------- scratch (device globals; no runtime allocation) ----------
__device__ int g_cnt0[N_DST0];
__device__ int g_cur0[N_DST0];
__device__ int g_off0[N_DST0 + 1];
__device__ int g_src0[N_E0];
__device__ int g_cnt1[N_DST1];
__device__ int g_cur1[N_DST1];
__device__ int g_off1[N_DST1 + 1];
__device__ int g_src1[N_E1];

__device__ __align__(16) __nv_bfloat16 g_xhi[(size_t)N_DST0 * KPAD];
__device__ __align__(16) __nv_bfloat16 g_xlo[(size_t)N_DST0 * KPAD];
__device__ __align__(16) __nv_bfloat16 g_ahi[(size_t)N_DST0 * KPAD];
__device__ __align__(16) __nv_bfloat16 g_alo[(size_t)N_DST0 * KPAD];
__device__ __align__(16) __nv_bfloat16 g_wshi[256 * KPAD];   // [n][k]  (W^T)
__device__ __align__(16) __nv_bfloat16 g_wslo[256 * KPAD];
__device__ __align__(16) __nv_bfloat16 g_wnhi[256 * KPAD];
__device__ __align__(16) __nv_bfloat16 g_wnlo[256 * KPAD];

__device__ float g_h    [(size_t)N_DST0 * HID];
__device__ float g_hagg1[(size_t)N_DST1 * HID];

__device__ __forceinline__ void split_bf16(float v, __nv_bfloat16& h, __nv_bfloat16& l) {
    h = __float2bfloat16(v);
    l = __float2bfloat16(v - __bfloat162float(h));
}

// ---------------- CSR build --------------------------------------------------
__global__ void k_zero() {
    int i = blockIdx.x * blockDim.x + threadIdx.x;
    if (i < N_DST0) { g_cnt0[i] = 0; g_cur0[i] = 0; }
    if (i < N_DST1) { g_cnt1[i] = 0; g_cur1[i] = 0; }
}

// fused: edge counting + weight hi/lo prep (independent work, one launch)
#define CNT_BLKS  ((N_E0 + 255) / 256)           // 1075
#define PW_BLKS   ((2 * 256 * KPAD + 255) / 256) // 1280
__global__ void k_count_prepw(const int* __restrict__ e0_dst, const int* __restrict__ e1_dst,
                              const float* __restrict__ Ws, const float* __restrict__ Wn) {
    int bx = blockIdx.x;
    if (bx < CNT_BLKS) {
        int i = bx * 256 + threadIdx.x;
        if (i < N_E0) atomicAdd(&g_cnt0[e0_dst[i]], 1);
        if (i < N_E1) atomicAdd(&g_cnt1[e1_dst[i]], 1);
    } else {
        int idx = (bx - CNT_BLKS) * 256 + threadIdx.x;
        if (idx >= 2 * 256 * KPAD) return;
        int m = idx / (256 * KPAD);
        int r = idx % (256 * KPAD);
        int n = r / KPAD;
        int k = r % KPAD;
        const float* W = m ? Wn : Ws;
        float v = (k < F_IN) ? W[(size_t)k * HID + n] : 0.0f;
        __nv_bfloat16 h, l; split_bf16(v, h, l);
        if (m) { g_wnhi[n * KPAD + k] = h; g_wnlo[n * KPAD + k] = l; }
        else   { g_wshi[n * KPAD + k] = h; g_wslo[n * KPAD + k] = l; }
    }
}

__device__ void scan_excl(const int* cnt, int* off, int n) {
    __shared__ int wsum[32];
    __shared__ int carry;
    const int t = threadIdx.x, lane = t & 31, w = t >> 5;
    if (t == 0) carry = 0;
    __syncthreads();
    for (int base = 0; base < n; base += 1024) {
        int i = base + t;
        int v = (i < n) ? cnt[i] : 0;
        int s = v;
        #pragma unroll
        for (int d = 1; d < 32; d <<= 1) { int u = __shfl_up_sync(~0u, s, d); if (lane >= d) s += u; }
        if (lane == 31) wsum[w] = s;
        __syncthreads();
        if (w == 0) {
            int ws = wsum[lane];
            #pragma unroll
            for (int d = 1; d < 32; d <<= 1) { int u = __shfl_up_sync(~0u, ws, d); if (lane >= d) ws += u; }
            wsum[lane] = ws;
        }
        __syncthreads();
        int woff = (w > 0) ? wsum[w - 1] : 0;
        if (i < n) off[i] = carry + woff + s - v;
        __syncthreads();
        if (t == 0) carry += wsum[31];
        __syncthreads();
    }
    if (threadIdx.x == 0) off[n] = carry;
}

__global__ void k_scan() {
    if (blockIdx.x == 0) scan_excl(g_cnt0, g_off0, N_DST0);
    else                 scan_excl(g_cnt1, g_off1, N_DST1);
}

// fused: edge scatter + x hi/lo prep
#define PX_BLKS ((N_DST0 * P2 + 255) / 256)   // 13750
__global__ void k_scatter_prepx(const int* __restrict__ e0_src, const int* __restrict__ e0_dst,
                                const int* __restrict__ e1_src, const int* __restrict__ e1_dst,
                                const float* __restrict__ x) {
    int bx = blockIdx.x;
    if (bx < CNT_BLKS) {
        int i = bx * 256 + threadIdx.x;
        if (i < N_E0) {
            int d = e0_dst[i];
            int p = atomicAdd(&g_cur0[d], 1);
            g_src0[g_off0[d] + p] = e0_src[i];
        }
        if (i < N_E1) {
            int d = e1_dst[i];
            int p = atomicAdd(&g_cur1[d], 1);
            g_src1[g_off1[d] + p] = e1_src[i];
        }
    } else {
        int idx = (bx - CNT_BLKS) * 256 + threadIdx.x;
        if (idx >= N_DST0 * P2) return;
        int row = idx / P2;
        int p   = idx % P2;
        float2 v = make_float2(0.f, 0.f);
        if (p < F2) v = reinterpret_cast<const float2*>(x)[(size_t)row * F2 + p];
        __nv_bfloat16 hx, lx, hy, ly;
        split_bf16(v.x, hx, lx);
        split_bf16(v.y, hy, ly);
        __nv_bfloat162 hp; hp.x = hx; hp.y = hy;
        __nv_bfloat162 lp; lp.x = lx; lp.y = ly;
        reinterpret_cast<__nv_bfloat162*>(g_xhi)[(size_t)row * P2 + p] = hp;
        reinterpret_cast<__nv_bfloat162*>(g_xlo)[(size_t)row * P2 + p] = lp;
    }
}

// ---------------- layer-0 mean aggregation (big gather) ----------------------
// 128 threads/block, 4-edge unroll: 12 independent LDG.64 in flight per thread.
__global__ void k_agg0(const float* __restrict__ x) {
    const int dst = blockIdx.x;
    const int beg = g_off0[dst];
    const int end = g_off0[dst + 1];
    const int t   = threadIdx.x;

    float2 acc0 = make_float2(0.f, 0.f);
    float2 acc1 = make_float2(0.f, 0.f);
    float2 acc2 = make_float2(0.f, 0.f);
    const bool has3 = (t + 256) < F2;

    int e = beg;
    for (; e + 4 <= end; e += 4) {
        const float2* r0 = reinterpret_cast<const float2*>(x + (size_t)g_src0[e + 0] * F_IN);
        const float2* r1 = reinterpret_cast<const float2*>(x + (size_t)g_src0[e + 1] * F_IN);
        const float2* r2 = reinterpret_cast<const float2*>(x + (size_t)g_src0[e + 2] * F_IN);
        const float2* r3 = reinterpret_cast<const float2*>(x + (size_t)g_src0[e + 3] * F_IN);
        float2 a0 = __ldg(r0 + t),       b0 = __ldg(r1 + t),       c0 = __ldg(r2 + t),       d0 = __ldg(r3 + t);
        float2 a1 = __ldg(r0 + t + 128), b1 = __ldg(r1 + t + 128), c1 = __ldg(r2 + t + 128), d1 = __ldg(r3 + t + 128);
        acc0.x += a0.x + b0.x + c0.x + d0.x;
        acc0.y += a0.y + b0.y + c0.y + d0.y;
        acc1.x += a1.x + b1.x + c1.x + d1.x;
        acc1.y += a1.y + b1.y + c1.y + d1.y;
        if (has3) {
            float2 a2 = __ldg(r0 + t + 256), b2 = __ldg(r1 + t + 256);
            float2 c2 = __ldg(r2 + t + 256), d2 = __ldg(r3 + t + 256);
            acc2.x += a2.x + b2.x + c2.x + d2.x;
            acc2.y += a2.y + b2.y + c2.y + d2.y;
        }
    }
    for (; e < end; ++e) {
        const float2* row = reinterpret_cast<const float2*>(x + (size_t)g_src0[e] * F_IN);
        float2 v0 = __ldg(row + t);
        float2 v1 = __ldg(row + t + 128);
        acc0.x += v0.x; acc0.y += v0.y;
        acc1.x += v1.x; acc1.y += v1.y;
        if (has3) {
            float2 v2 = __ldg(row + t + 256);
            acc2.x += v2.x; acc2.y += v2.y;
        }
    }

    const float inv = (end > beg) ? 1.0f / (float)(end - beg) : 0.0f;
    __nv_bfloat162* ohi = reinterpret_cast<__nv_bfloat162*>(g_ahi) + (size_t)dst * P2;
    __nv_bfloat162* olo = reinterpret_cast<__nv_bfloat162*>(g_alo) + (size_t)dst * P2;
    float2 accs[3] = {acc0, acc1, acc2};
    #pragma unroll
    for (int j = 0; j < 3; ++j) {
        int p = t + j * 128;
        if (p >= P2) break;
        float vx = (p < F2) ? accs[j].x * inv : 0.f;
        float vy = (p < F2) ? accs[j].y * inv : 0.f;
        __nv_bfloat16 hx, lx, hy, ly;
        split_bf16(vx, hx, lx);
        split_bf16(vy, hy, ly);
        __nv_bfloat162 hp; hp.x = hx; hp.y = hy;
        __nv_bfloat162 lp; lp.x = lx; lp.y = ly;
        ohi[p] = hp;
        olo[p] = lp;
    }
}

// ---------------- tensor-core GEMM via mma.sync (HMMA, sm_80+ PTX) ----------
// h = relu([Xd | Hagg] @ [Ws; Wn] + b0), 3-term bf16 split into f32 acc.
// CTA tile 128x64; grid (86, 4); 8 warps = 4(M) x 2(N); warp tile 32x32.
// Single flattened 40-chunk pipeline spanning both phases.
#define BK        32
#define ROWP      40                       // padded row length (bf16)
#define A_TERM    (128 * ROWP * 2)         // 10240 B
#define B_TERM    (64 * ROWP * 2)          // 5120 B
#define BUF_SZ    (2 * A_TERM + 2 * B_TERM)  // 30720 B
#define GEMM_SMEM (2 * BUF_SZ)             // 61440 B
#define NCH       40                       // 2 phases x 20 K-chunks

#define CP16(dst, src, pred) \
    asm volatile("cp.async.cg.shared.global [%0], [%1], 16, %2;" \
                 :: "r"(dst), "l"(src), "r"(pred))
#define CP_COMMIT() asm volatile("cp.async.commit_group;" ::: "memory")
#define CP_WAIT(n)  asm volatile("cp.async.wait_group %0;" :: "n"(n) : "memory")

__device__ __forceinline__ uint32_t smem_u32(const void* p) {
    uint32_t a;
    asm("{ .reg .u64 t; cvta.to.shared.u64 t, %1; cvt.u32.u64 %0, t; }" : "=r"(a) : "l"(p));
    return a;
}

__device__ __forceinline__ void mma_bf16(float* d,
                                         const uint32_t* a, const uint32_t* b) {
    asm volatile(
        "mma.sync.aligned.m16n8k16.row.col.f32.bf16.bf16.f32 "
        "{%0,%1,%2,%3}, {%4,%5,%6,%7}, {%8,%9}, {%0,%1,%2,%3};"
        : "+f"(d[0]), "+f"(d[1]), "+f"(d[2]), "+f"(d[3])
        : "r"(a[0]), "r"(a[1]), "r"(a[2]), "r"(a[3]), "r"(b[0]), "r"(b[1]));
}

__global__ __launch_bounds__(256, 3)
void k_gemm_mma(const float* __restrict__ bias) {
    extern __shared__ char smem[];
    const uint32_t sb = smem_u32(smem);
    const int tid  = threadIdx.x;
    const int lane = tid & 31;
    const int wid  = tid >> 5;
    const int warpM = wid & 3;            // 0..3
    const int warpN = wid >> 2;           // 0..1
    const int g  = lane >> 2;             // 0..7
    const int tg = lane & 3;              // 0..3
    const int rowBase = blockIdx.x * 128;
    const int colBase = blockIdx.y * 64;

    auto issue = [&](int c) {
        const int ph = (c >= 20);
        const int kb = (c - ph * 20) * BK;
        const __nv_bfloat16* Ah = ph ? g_ahi : g_xhi;
        const __nv_bfloat16* Al = ph ? g_alo : g_xlo;
        const __nv_bfloat16* Bh = ph ? g_wnhi : g_wshi;
        const __nv_bfloat16* Bl = ph ? g_wnlo : g_wslo;
        const uint32_t bufb = sb + (uint32_t)(c & 1) * BUF_SZ;

        #pragma unroll
        for (int u = 0; u < 2; ++u) {
            int idx = tid + u * 256;          // 0..511
            int row = idx >> 2, v = idx & 3;
            int grow = rowBase + row;
            int pr = (grow < N_DST0) ? 16 : 0;
            size_t gb = ((size_t)grow * KPAD + kb + v * 8) * 2;
            if (grow >= N_DST0) gb = 0;
            uint32_t so = bufb + (uint32_t)(row * (ROWP * 2) + v * 16);
            CP16(so,          (const char*)Ah + gb, pr);
            CP16(so + A_TERM, (const char*)Al + gb, pr);
        }
        {
            int row = tid >> 2, v = tid & 3;
            size_t gb = ((size_t)(colBase + row) * KPAD + kb + v * 8) * 2;
            uint32_t so = bufb + (uint32_t)(2 * A_TERM + row * (ROWP * 2) + v * 16);
            CP16(so,          (const char*)Bh + gb, 16);
            CP16(so + B_TERM, (const char*)Bl + gb, 16);
        }
    };

    float acc[2][4][4] = {};   // [mtile][ntile][reg]

    issue(0);
    CP_COMMIT();

    for (int c = 0; c < NCH; ++c) {
        if (c + 1 < NCH) { issue(c + 1); CP_COMMIT(); CP_WAIT(1); }
        else             { CP_WAIT(0); }
        __syncthreads();

        const char* buf = smem + (c & 1) * BUF_SZ;
        const char* Ahs = buf;
        const char* Als = buf + A_TERM;
        const char* Bhs = buf + 2 * A_TERM;
        const char* Bls = buf + 2 * A_TERM + B_TERM;

        #pragma unroll
        for (int kk = 0; kk < BK; kk += 16) {
            const int kbyte = kk * 2 + tg * 4;

            uint32_t aH[2][4];
            #pragma unroll
            for (int mt = 0; mt < 2; ++mt) {
                int r0 = warpM * 32 + mt * 16 + g;
                aH[mt][0] = *(const uint32_t*)(Ahs + r0 * (ROWP * 2) + kbyte);
                aH[mt][1] = *(const uint32_t*)(Ahs + (r0 + 8) * (ROWP * 2) + kbyte);
                aH[mt][2] = *(const uint32_t*)(Ahs + r0 * (ROWP * 2) + kbyte + 16);
                aH[mt][3] = *(const uint32_t*)(Ahs + (r0 + 8) * (ROWP * 2) + kbyte + 16);
            }
            uint32_t bH[4][2];
            #pragma unroll
            for (int nt = 0; nt < 4; ++nt) {
                int r = warpN * 32 + nt * 8 + g;
                bH[nt][0] = *(const uint32_t*)(Bhs + r * (ROWP * 2) + kbyte);
                bH[nt][1] = *(const uint32_t*)(Bhs + r * (ROWP * 2) + kbyte + 16);
            }
            #pragma unroll
            for (int mt = 0; mt < 2; ++mt)
                #pragma unroll
                for (int nt = 0; nt < 4; ++nt)
                    mma_bf16(acc[mt][nt], aH[mt], bH[nt]);

            uint32_t bL[4][2];
            #pragma unroll
            for (int nt = 0; nt < 4; ++nt) {
                int r = warpN * 32 + nt * 8 + g;
                bL[nt][0] = *(const uint32_t*)(Bls + r * (ROWP * 2) + kbyte);
                bL[nt][1] = *(const uint32_t*)(Bls + r * (ROWP * 2) + kbyte + 16);
            }
            #pragma unroll
            for (int mt = 0; mt < 2; ++mt)
                #pragma unroll
                for (int nt = 0; nt < 4; ++nt)
                    mma_bf16(acc[mt][nt], aH[mt], bL[nt]);

            uint32_t aL[2][4];
            #pragma unroll
            for (int mt = 0; mt < 2; ++mt) {
                int r0 = warpM * 32 + mt * 16 + g;
                aL[mt][0] = *(const uint32_t*)(Als + r0 * (ROWP * 2) + kbyte);
                aL[mt][1] = *(const uint32_t*)(Als + (r0 + 8) * (ROWP * 2) + kbyte);
                aL[mt][2] = *(const uint32_t*)(Als + r0 * (ROWP * 2) + kbyte + 16);
                aL[mt][3] = *(const uint32_t*)(Als + (r0 + 8) * (ROWP * 2) + kbyte + 16);
            }
            #pragma unroll
            for (int mt = 0; mt < 2; ++mt)
                #pragma unroll
                for (int nt = 0; nt < 4; ++nt)
                    mma_bf16(acc[mt][nt], aL[mt], bH[nt]);
        }
        __syncthreads();
    }

    // ---- epilogue: bias + relu, float2 stores ----
    float2 bv[4];
    #pragma unroll
    for (int nt = 0; nt < 4; ++nt) {
        int col = colBase + warpN * 32 + nt * 8 + tg * 2;
        bv[nt].x = __ldg(bias + col);
        bv[nt].y = __ldg(bias + col + 1);
    }
    #pragma unroll
    for (int mt = 0; mt < 2; ++mt) {
        #pragma unroll
        for (int half = 0; half < 2; ++half) {
            int row = rowBase + warpM * 32 + mt * 16 + g + half * 8;
            if (row >= N_DST0) continue;
            #pragma unroll
            for (int nt = 0; nt < 4; ++nt) {
                int col = colBase + warpN * 32 + nt * 8 + tg * 2;
                float2 o;
                o.x = fmaxf(acc[mt][nt][half * 2 + 0] + bv[nt].x, 0.f);
                o.y = fmaxf(acc[mt][nt][half * 2 + 1] + bv[nt].y, 0.f);
                *(float2*)(g_h + (size_t)row * HID + col) = o;
            }
        }
    }
}

// ---------------- layer-1 mean aggregation -----------------------------------
__global__ void k_agg1() {
    const int dst = blockIdx.x;
    const int beg = g_off1[dst];
    const int end = g_off1[dst + 1];
    const int t   = threadIdx.x;

    float acc = 0.f;
    for (int e = beg; e < end; ++e)
        acc += g_h[(size_t)g_src1[e] * HID + t];

    const float inv = (end > beg) ? 1.0f / (float)(end - beg) : 0.0f;
    g_hagg1[(size_t)dst * HID + t] = acc * inv;
}

// ---------------- output layer -------------------------------------------------
__global__ void k_out(const float* __restrict__ Ws1,
                      const float* __restrict__ Wn1,
                      const float* __restrict__ b1,
                      float* __restrict__ out) {
    __shared__ float hd[HID];
    __shared__ float ha[HID];
    const int dst = blockIdx.x;
    for (int i = threadIdx.x; i < HID; i += blockDim.x) {
        hd[i] = g_h[(size_t)dst * HID + i];
        ha[i] = g_hagg1[(size_t)dst * HID + i];
    }
    __syncthreads();
    const int c = threadIdx.x;
    if (c < NCLS) {
        float s = b1[c];
        #pragma unroll 4
        for (int k = 0; k < HID; ++k)
            s += hd[k] * Ws1[k * NCLS + c] + ha[k] * Wn1[k * NCLS + c];
        out[dst * NCLS + c] = s;
    }
}

// ---------------- launch (single stream, graph-capture safe) -----------------
extern "C" void kernel_launch(void* const* d_in, const int* in_sizes, int n_in,
                              void* d_out, int out_size) {
    const float* x      = (const float*)d_in[0];
    const float* Wself0 = (const float*)d_in[1];
    const float* Wneigh0= (const float*)d_in[2];
    const float* b0     = (const float*)d_in[3];
    const float* Wself1 = (const float*)d_in[4];
    const float* Wneigh1= (const float*)d_in[5];
    const float* b1     = (const float*)d_in[6];
    const int*   e0_src = (const int*)d_in[7];
    const int*   e0_dst = (const int*)d_in[8];
    const int*   e1_src = (const int*)d_in[9];
    const int*   e1_dst = (const int*)d_in[10];
    float* out = (float*)d_out;

    static bool attr_set = false;
    if (!attr_set) {
        cudaFuncSetAttribute(k_gemm_mma, cudaFuncAttributeMaxDynamicSharedMemorySize, GEMM_SMEM);
        attr_set = true;
    }

    k_zero          <<<(N_DST0 + 255) / 256, 256>>>();
    k_count_prepw   <<<CNT_BLKS + PW_BLKS, 256>>>(e0_dst, e1_dst, Wself0, Wneigh0);
    k_scan          <<<2, 1024>>>();
    k_scatter_prepx <<<CNT_BLKS + PX_BLKS, 256>>>(e0_src, e0_dst, e1_src, e1_dst, x);
    k_agg0          <<<N_DST0, 128>>>(x);
    k_gemm_mma      <<<dim3((N_DST0 + 127) / 128, 4), 256, GEMM_SMEM>>>(b0);
    k_agg1          <<<N_DST1, 256>>>();
    k_out           <<<N_DST1, 64>>>(Wself1, Wneigh1, b1, out);
}

// round 8
// speedup vs baseline: 1.2325x; 1.0927x over previous
#include <cuda_runtime.h>
#include <cuda_bf16.h>
#include <cstdint>
#include <cstddef>

// Problem constants
#define N_SRC0   286000
#define N_DST0   11000
#define N_E0     275000
#define N_DST1   1000
#define N_E1     10000
#define F_IN     602
#define HID      256
#define NCLS     41
#define KPAD     640          // 20 chunks of 32
#define F2       (F_IN / 2)   // 301
#define P2       (KPAD / 2)   // 320

// ---------------- scratch (device globals; no runtime allocation) ----------
__device__ int g_cnt0[N_DST0];
__device__ int g_cur0[N_DST0];
__device__ int g_off0[N_DST0 + 1];
__device__ int g_src0[N_E0];
__device__ int g_cnt1[N_DST1];
__device__ int g_cur1[N_DST1];
__device__ int g_off1[N_DST1 + 1];
__device__ int g_src1[N_E1];

// tf32-rounded fp32 operand buffers (padded to KPAD)
__device__ __align__(16) float g_xt  [(size_t)N_DST0 * KPAD];   // x[:11000] rna-rounded
__device__ __align__(16) float g_hagg[(size_t)N_DST0 * KPAD];   // layer-0 mean agg, rna-rounded
__device__ __align__(16) float g_wts [256 * KPAD];              // Wself0^T  [n][k]
__device__ __align__(16) float g_wtn [256 * KPAD];              // Wneigh0^T [n][k]

__device__ float g_h    [(size_t)N_DST0 * HID];
__device__ float g_hagg1[(size_t)N_DST1 * HID];

// round-to-nearest tf32 (unbiased; raw truncation would bias the output ~7e-4)
__device__ __forceinline__ float tf32r(float v) {
    uint32_t o;
    asm("cvt.rna.tf32.f32 %0, %1;" : "=r"(o) : "f"(v));
    return __uint_as_float(o);
}

// ---------------- CSR build --------------------------------------------------
__global__ void k_zero() {
    int i = blockIdx.x * blockDim.x + threadIdx.x;
    if (i < N_DST0) { g_cnt0[i] = 0; g_cur0[i] = 0; }
    if (i < N_DST1) { g_cnt1[i] = 0; g_cur1[i] = 0; }
}

// fused: edge counting + weight transpose/round prep
#define CNT_BLKS  ((N_E0 + 255) / 256)           // 1075
#define PW_BLKS   ((2 * 256 * KPAD + 255) / 256) // 1280
__global__ void k_count_prepw(const int* __restrict__ e0_dst, const int* __restrict__ e1_dst,
                              const float* __restrict__ Ws, const float* __restrict__ Wn) {
    int bx = blockIdx.x;
    if (bx < CNT_BLKS) {
        int i = bx * 256 + threadIdx.x;
        if (i < N_E0) atomicAdd(&g_cnt0[e0_dst[i]], 1);
        if (i < N_E1) atomicAdd(&g_cnt1[e1_dst[i]], 1);
    } else {
        int idx = (bx - CNT_BLKS) * 256 + threadIdx.x;
        if (idx >= 2 * 256 * KPAD) return;
        int m = idx / (256 * KPAD);
        int r = idx % (256 * KPAD);
        int n = r / KPAD;
        int k = r % KPAD;
        const float* W = m ? Wn : Ws;
        float v = (k < F_IN) ? tf32r(W[(size_t)k * HID + n]) : 0.0f;
        if (m) g_wtn[n * KPAD + k] = v;
        else   g_wts[n * KPAD + k] = v;
    }
}

__device__ void scan_excl(const int* cnt, int* off, int n) {
    __shared__ int wsum[32];
    __shared__ int carry;
    const int t = threadIdx.x, lane = t & 31, w = t >> 5;
    if (t == 0) carry = 0;
    __syncthreads();
    for (int base = 0; base < n; base += 1024) {
        int i = base + t;
        int v = (i < n) ? cnt[i] : 0;
        int s = v;
        #pragma unroll
        for (int d = 1; d < 32; d <<= 1) { int u = __shfl_up_sync(~0u, s, d); if (lane >= d) s += u; }
        if (lane == 31) wsum[w] = s;
        __syncthreads();
        if (w == 0) {
            int ws = wsum[lane];
            #pragma unroll
            for (int d = 1; d < 32; d <<= 1) { int u = __shfl_up_sync(~0u, ws, d); if (lane >= d) ws += u; }
            wsum[lane] = ws;
        }
        __syncthreads();
        int woff = (w > 0) ? wsum[w - 1] : 0;
        if (i < n) off[i] = carry + woff + s - v;
        __syncthreads();
        if (t == 0) carry += wsum[31];
        __syncthreads();
    }
    if (threadIdx.x == 0) off[n] = carry;
}

__global__ void k_scan() {
    if (blockIdx.x == 0) scan_excl(g_cnt0, g_off0, N_DST0);
    else                 scan_excl(g_cnt1, g_off1, N_DST1);
}

// fused: edge scatter + x round/pad prep
#define PX_BLKS ((N_DST0 * P2 + 255) / 256)   // 13750
__global__ void k_scatter_prepx(const int* __restrict__ e0_src, const int* __restrict__ e0_dst,
                                const int* __restrict__ e1_src, const int* __restrict__ e1_dst,
                                const float* __restrict__ x) {
    int bx = blockIdx.x;
    if (bx < CNT_BLKS) {
        int i = bx * 256 + threadIdx.x;
        if (i < N_E0) {
            int d = e0_dst[i];
            int p = atomicAdd(&g_cur0[d], 1);
            g_src0[g_off0[d] + p] = e0_src[i];
        }
        if (i < N_E1) {
            int d = e1_dst[i];
            int p = atomicAdd(&g_cur1[d], 1);
            g_src1[g_off1[d] + p] = e1_src[i];
        }
    } else {
        int idx = (bx - CNT_BLKS) * 256 + threadIdx.x;
        if (idx >= N_DST0 * P2) return;
        int row = idx / P2;
        int p   = idx % P2;
        float2 v = make_float2(0.f, 0.f);
        if (p < F2) v = reinterpret_cast<const float2*>(x)[(size_t)row * F2 + p];
        float2 o; o.x = tf32r(v.x); o.y = tf32r(v.y);
        reinterpret_cast<float2*>(g_xt)[(size_t)row * P2 + p] = o;
    }
}

// ---------------- layer-0 mean aggregation (big gather) ----------------------
// 128 threads/block, 4-edge unroll: 12 independent LDG.64 in flight per thread.
__global__ void k_agg0(const float* __restrict__ x) {
    const int dst = blockIdx.x;
    const int beg = g_off0[dst];
    const int end = g_off0[dst + 1];
    const int t   = threadIdx.x;

    float2 acc0 = make_float2(0.f, 0.f);
    float2 acc1 = make_float2(0.f, 0.f);
    float2 acc2 = make_float2(0.f, 0.f);
    const bool has3 = (t + 256) < F2;

    int e = beg;
    for (; e + 4 <= end; e += 4) {
        const float2* r0 = reinterpret_cast<const float2*>(x + (size_t)g_src0[e + 0] * F_IN);
        const float2* r1 = reinterpret_cast<const float2*>(x + (size_t)g_src0[e + 1] * F_IN);
        const float2* r2 = reinterpret_cast<const float2*>(x + (size_t)g_src0[e + 2] * F_IN);
        const float2* r3 = reinterpret_cast<const float2*>(x + (size_t)g_src0[e + 3] * F_IN);
        float2 a0 = __ldg(r0 + t),       b0 = __ldg(r1 + t),       c0 = __ldg(r2 + t),       d0 = __ldg(r3 + t);
        float2 a1 = __ldg(r0 + t + 128), b1 = __ldg(r1 + t + 128), c1 = __ldg(r2 + t + 128), d1 = __ldg(r3 + t + 128);
        acc0.x += a0.x + b0.x + c0.x + d0.x;
        acc0.y += a0.y + b0.y + c0.y + d0.y;
        acc1.x += a1.x + b1.x + c1.x + d1.x;
        acc1.y += a1.y + b1.y + c1.y + d1.y;
        if (has3) {
            float2 a2 = __ldg(r0 + t + 256), b2 = __ldg(r1 + t + 256);
            float2 c2 = __ldg(r2 + t + 256), d2 = __ldg(r3 + t + 256);
            acc2.x += a2.x + b2.x + c2.x + d2.x;
            acc2.y += a2.y + b2.y + c2.y + d2.y;
        }
    }
    for (; e < end; ++e) {
        const float2* row = reinterpret_cast<const float2*>(x + (size_t)g_src0[e] * F_IN);
        float2 v0 = __ldg(row + t);
        float2 v1 = __ldg(row + t + 128);
        acc0.x += v0.x; acc0.y += v0.y;
        acc1.x += v1.x; acc1.y += v1.y;
        if (has3) {
            float2 v2 = __ldg(row + t + 256);
            acc2.x += v2.x; acc2.y += v2.y;
        }
    }

    const float inv = (end > beg) ? 1.0f / (float)(end - beg) : 0.0f;
    float2* o = reinterpret_cast<float2*>(g_hagg) + (size_t)dst * P2;
    float2 accs[3] = {acc0, acc1, acc2};
    #pragma unroll
    for (int j = 0; j < 3; ++j) {
        int p = t + j * 128;
        if (p >= P2) break;
        float2 ov;
        ov.x = (p < F2) ? tf32r(accs[j].x * inv) : 0.f;
        ov.y = (p < F2) ? tf32r(accs[j].y * inv) : 0.f;
        o[p] = ov;
    }
}

// ---------------- tensor-core GEMM via mma.sync (TF32, sm_80+ PTX) ----------
// h = relu([Xd | Hagg] @ [Ws; Wn] + b0), single-pass tf32 (inputs rna-rounded).
// CTA tile 128x64; grid (86, 4); 8 warps = 4(M) x 2(N); warp tile 32x32.
// Flattened 40-chunk double-buffered cp.async pipeline spanning both phases.
#define BK        32
#define ROWPF     36                       // padded row length (floats) -> conflict-free frags
#define A_T       (128 * ROWPF * 4)        // 18432 B
#define B_T       (64 * ROWPF * 4)         // 9216 B
#define BUF_SZ    (A_T + B_T)              // 27648 B
#define GEMM_SMEM (2 * BUF_SZ)             // 55296 B
#define NCH       40                       // 2 phases x 20 K-chunks

#define CP16(dst, src, pred) \
    asm volatile("cp.async.cg.shared.global [%0], [%1], 16, %2;" \
                 :: "r"(dst), "l"(src), "r"(pred))
#define CP_COMMIT() asm volatile("cp.async.commit_group;" ::: "memory")
#define CP_WAIT(n)  asm volatile("cp.async.wait_group %0;" :: "n"(n) : "memory")

__device__ __forceinline__ uint32_t smem_u32(const void* p) {
    uint32_t a;
    asm("{ .reg .u64 t; cvta.to.shared.u64 t, %1; cvt.u32.u64 %0, t; }" : "=r"(a) : "l"(p));
    return a;
}

__device__ __forceinline__ void mma_tf32(float* d,
                                         const uint32_t* a, const uint32_t* b) {
    asm volatile(
        "mma.sync.aligned.m16n8k8.row.col.f32.tf32.tf32.f32 "
        "{%0,%1,%2,%3}, {%4,%5,%6,%7}, {%8,%9}, {%0,%1,%2,%3};"
        : "+f"(d[0]), "+f"(d[1]), "+f"(d[2]), "+f"(d[3])
        : "r"(a[0]), "r"(a[1]), "r"(a[2]), "r"(a[3]), "r"(b[0]), "r"(b[1]));
}

__global__ __launch_bounds__(256, 3)
void k_gemm_mma(const float* __restrict__ bias) {
    extern __shared__ char smem[];
    const uint32_t sb = smem_u32(smem);
    const int tid  = threadIdx.x;
    const int lane = tid & 31;
    const int wid  = tid >> 5;
    const int warpM = wid & 3;            // 0..3
    const int warpN = wid >> 2;           // 0..1
    const int g  = lane >> 2;             // 0..7
    const int tg = lane & 3;              // 0..3
    const int rowBase = blockIdx.x * 128;
    const int colBase = blockIdx.y * 64;

    auto issue = [&](int c) {
        const int ph = (c >= 20);
        const int kb = (c - ph * 20) * BK;
        const float* A = ph ? g_hagg : g_xt;
        const float* B = ph ? g_wtn : g_wts;
        const uint32_t bufb = sb + (uint32_t)(c & 1) * BUF_SZ;

        // A: 128 rows x 32 floats = 1024 x 16B -> 4 per thread
        #pragma unroll
        for (int u = 0; u < 4; ++u) {
            int idx = tid + u * 256;          // 0..1023
            int row = idx >> 3, v = idx & 7;
            int grow = rowBase + row;
            int pr = (grow < N_DST0) ? 16 : 0;
            size_t gb = ((size_t)grow * KPAD + kb + v * 4) * 4;  // bytes
            if (grow >= N_DST0) gb = 0;
            uint32_t so = bufb + (uint32_t)(row * (ROWPF * 4) + v * 16);
            CP16(so, (const char*)A + gb, pr);
        }
        // B: 64 rows x 32 floats = 512 x 16B -> 2 per thread
        #pragma unroll
        for (int u = 0; u < 2; ++u) {
            int idx = tid + u * 256;          // 0..511
            int row = idx >> 3, v = idx & 7;
            size_t gb = ((size_t)(colBase + row) * KPAD + kb + v * 4) * 4;
            uint32_t so = bufb + (uint32_t)(A_T + row * (ROWPF * 4) + v * 16);
            CP16(so, (const char*)B + gb, 16);
        }
    };

    float acc[2][4][4] = {};   // [mtile][ntile][reg]

    issue(0);
    CP_COMMIT();

    for (int c = 0; c < NCH; ++c) {
        if (c + 1 < NCH) { issue(c + 1); CP_COMMIT(); CP_WAIT(1); }
        else             { CP_WAIT(0); }
        __syncthreads();

        const char* buf = smem + (c & 1) * BUF_SZ;
        const char* As = buf;
        const char* Bs = buf + A_T;

        #pragma unroll
        for (int ks = 0; ks < 4; ++ks) {
            const int kbyte = (ks * 8 + tg) * 4;

            uint32_t a[2][4];
            #pragma unroll
            for (int mt = 0; mt < 2; ++mt) {
                int r0 = warpM * 32 + mt * 16 + g;
                a[mt][0] = *(const uint32_t*)(As + r0 * (ROWPF * 4) + kbyte);
                a[mt][1] = *(const uint32_t*)(As + (r0 + 8) * (ROWPF * 4) + kbyte);
                a[mt][2] = *(const uint32_t*)(As + r0 * (ROWPF * 4) + kbyte + 16);
                a[mt][3] = *(const uint32_t*)(As + (r0 + 8) * (ROWPF * 4) + kbyte + 16);
            }
            uint32_t b[4][2];
            #pragma unroll
            for (int nt = 0; nt < 4; ++nt) {
                int r = warpN * 32 + nt * 8 + g;
                b[nt][0] = *(const uint32_t*)(Bs + r * (ROWPF * 4) + kbyte);
                b[nt][1] = *(const uint32_t*)(Bs + r * (ROWPF * 4) + kbyte + 16);
            }
            #pragma unroll
            for (int mt = 0; mt < 2; ++mt)
                #pragma unroll
                for (int nt = 0; nt < 4; ++nt)
                    mma_tf32(acc[mt][nt], a[mt], b[nt]);
        }
        __syncthreads();
    }

    // ---- epilogue: bias + relu, float2 stores ----
    float2 bv[4];
    #pragma unroll
    for (int nt = 0; nt < 4; ++nt) {
        int col = colBase + warpN * 32 + nt * 8 + tg * 2;
        bv[nt].x = __ldg(bias + col);
        bv[nt].y = __ldg(bias + col + 1);
    }
    #pragma unroll
    for (int mt = 0; mt < 2; ++mt) {
        #pragma unroll
        for (int half = 0; half < 2; ++half) {
            int row = rowBase + warpM * 32 + mt * 16 + g + half * 8;
            if (row >= N_DST0) continue;
            #pragma unroll
            for (int nt = 0; nt < 4; ++nt) {
                int col = colBase + warpN * 32 + nt * 8 + tg * 2;
                float2 o;
                o.x = fmaxf(acc[mt][nt][half * 2 + 0] + bv[nt].x, 0.f);
                o.y = fmaxf(acc[mt][nt][half * 2 + 1] + bv[nt].y, 0.f);
                *(float2*)(g_h + (size_t)row * HID + col) = o;
            }
        }
    }
}

// ---------------- layer-1 mean aggregation -----------------------------------
__global__ void k_agg1() {
    const int dst = blockIdx.x;
    const int beg = g_off1[dst];
    const int end = g_off1[dst + 1];
    const int t   = threadIdx.x;

    float acc = 0.f;
    for (int e = beg; e < end; ++e)
        acc += g_h[(size_t)g_src1[e] * HID + t];

    const float inv = (end > beg) ? 1.0f / (float)(end - beg) : 0.0f;
    g_hagg1[(size_t)dst * HID + t] = acc * inv;
}

// ---------------- output layer -------------------------------------------------
__global__ void k_out(const float* __restrict__ Ws1,
                      const float* __restrict__ Wn1,
                      const float* __restrict__ b1,
                      float* __restrict__ out) {
    __shared__ float hd[HID];
    __shared__ float ha[HID];
    const int dst = blockIdx.x;
    for (int i = threadIdx.x; i < HID; i += blockDim.x) {
        hd[i] = g_h[(size_t)dst * HID + i];
        ha[i] = g_hagg1[(size_t)dst * HID + i];
    }
    __syncthreads();
    const int c = threadIdx.x;
    if (c < NCLS) {
        float s = b1[c];
        #pragma unroll 4
        for (int k = 0; k < HID; ++k)
            s += hd[k] * Ws1[k * NCLS + c] + ha[k] * Wn1[k * NCLS + c];
        out[dst * NCLS + c] = s;
    }
}

// ---------------- launch (single stream, graph-capture safe) -----------------
extern "C" void kernel_launch(void* const* d_in, const int* in_sizes, int n_in,
                              void* d_out, int out_size) {
    const float* x      = (const float*)d_in[0];
    const float* Wself0 = (const float*)d_in[1];
    const float* Wneigh0= (const float*)d_in[2];
    const float* b0     = (const float*)d_in[3];
    const float* Wself1 = (const float*)d_in[4];
    const float* Wneigh1= (const float*)d_in[5];
    const float* b1     = (const float*)d_in[6];
    const int*   e0_src = (const int*)d_in[7];
    const int*   e0_dst = (const int*)d_in[8];
    const int*   e1_src = (const int*)d_in[9];
    const int*   e1_dst = (const int*)d_in[10];
    float* out = (float*)d_out;

    static bool attr_set = false;
    if (!attr_set) {
        cudaFuncSetAttribute(k_gemm_mma, cudaFuncAttributeMaxDynamicSharedMemorySize, GEMM_SMEM);
        attr_set = true;
    }

    k_zero          <<<(N_DST0 + 255) / 256, 256>>>();
    k_count_prepw   <<<CNT_BLKS + PW_BLKS, 256>>>(e0_dst, e1_dst, Wself0, Wneigh0);
    k_scan          <<<2, 1024>>>();
    k_scatter_prepx <<<CNT_BLKS + PX_BLKS, 256>>>(e0_src, e0_dst, e1_src, e1_dst, x);
    k_agg0          <<<N_DST0, 128>>>(x);
    k_gemm_mma      <<<dim3((N_DST0 + 127) / 128, 4), 256, GEMM_SMEM>>>(b0);
    k_agg1          <<<N_DST1, 256>>>();
    k_out           <<<N_DST1, 64>>>(Wself1, Wneigh1, b1, out);
}